// round 1
// baseline (speedup 1.0000x reference)
#include <cuda_runtime.h>
#include <math.h>

// Problem constants
#define NND   25600                  // num nodes (B*SEQ)
#define DCH   128                    // channels
#define SEQL  25
#define HHH   8
#define DHD   16
#define PS    (25600*128)            // plane stride for D=128 blade-major arrays
#define PS2   (25600*256)            // plane stride for 2D=256 arrays
#define UNIT  (8*25600*128)          // one [8][N][128] tensor, floats

// Scratch: 12 units = 1.26 GB (allowed: __device__ globals, no allocs)
__device__ float g_scratch[12u * (unsigned)UNIT];
// Expanded per-grade weights: [grade(4)][out][in] for each of 9 linears
__device__ float g_w4[917504];

// ---------------- weight expansion: w[o][m][g] -> out[g][o*m] ----------------
__global__ void k_expand(const float* __restrict__ w, float* __restrict__ out, int total) {
    int i = blockIdx.x * blockDim.x + threadIdx.x;
    if (i < total) {
        int om = total >> 2;           // O*M
        int g = i / om, r = i % om;
        out[i] = w[r * 4 + g];
    }
}

// -------- transpose [N,D,8] -> blade-major [8][N][D], fused with mv_layernorm(ln1) --------
__global__ void k_tr_ln1(const float* __restrict__ src, const float* __restrict__ a,
                         float* __restrict__ srcT, float* __restrict__ h1) {
    int n = blockIdx.x, c = threadIdx.x;
    const float* p = src + ((size_t)n * DCH + c) * 8;
    float4 x0 = *(const float4*)p;
    float4 x1 = *(const float4*)(p + 4);
    float v[8] = {x0.x, x0.y, x0.z, x0.w, x1.x, x1.y, x1.z, x1.w};
    float s = 0.f;
    #pragma unroll
    for (int i = 0; i < 8; i++) s += v[i] * v[i];
    float nr = sqrtf(s);
    __shared__ float red[128];
    red[c] = nr; __syncthreads();
    for (int st = 64; st > 0; st >>= 1) {
        if (c < st) red[c] += red[c + st];
        __syncthreads();
    }
    float inv = 1.f / (red[0] * (1.f / 128.f) + 1e-6f);
    float ac = a[c];
    size_t base = (size_t)n * DCH + c;
    #pragma unroll
    for (int i = 0; i < 8; i++) {
        srcT[(size_t)i * PS + base] = v[i];
        h1[(size_t)i * PS + base]   = ac * v[i] * inv;
    }
}

// -------- mv_layernorm on blade-major [8][N][128], optional residual add --------
__global__ void k_ln(const float* __restrict__ x, const float* __restrict__ a,
                     const float* __restrict__ res, float* __restrict__ out) {
    int n = blockIdx.x, c = threadIdx.x;
    size_t base = (size_t)n * DCH + c;
    float v[8];
    #pragma unroll
    for (int i = 0; i < 8; i++) v[i] = x[(size_t)i * PS + base];
    float s = 0.f;
    #pragma unroll
    for (int i = 0; i < 8; i++) s += v[i] * v[i];
    float nr = sqrtf(s);
    __shared__ float red[128];
    red[c] = nr; __syncthreads();
    for (int st = 64; st > 0; st >>= 1) {
        if (c < st) red[c] += red[c + st];
        __syncthreads();
    }
    float inv = 1.f / (red[0] * (1.f / 128.f) + 1e-6f);
    float ac = a[c];
    #pragma unroll
    for (int i = 0; i < 8; i++) {
        float r = res ? res[(size_t)i * PS + base] : 0.f;
        out[(size_t)i * PS + base] = r + ac * v[i] * inv;
    }
}

// -------- blade-GEMM: Y[i][n][o] = sum_m A[i][n][m] * W[grade(i)][o][m] (+bias@blade0, +res) --------
__global__ __launch_bounds__(256, 2)
void k_sgemm(const float* __restrict__ A, const float* __restrict__ W,
             const float* __restrict__ bias, const float* __restrict__ Res,
             float* __restrict__ Y, int M, int N, int K) {
    const int blade = blockIdx.z;
    const int g = (blade == 0) ? 0 : (blade <= 3) ? 1 : (blade <= 6) ? 2 : 3;
    const float* Ab = A + (size_t)blade * M * K;
    const float* Wb = W + (size_t)g * N * K;
    float* Yb = Y + (size_t)blade * M * N;
    const float* Rb = Res ? (Res + (size_t)blade * M * N) : nullptr;

    const int bm0 = blockIdx.y * 128;
    const int bn0 = blockIdx.x * 128;

    __shared__ float As[16][132];
    __shared__ float Bs[16][132];

    const int tid = threadIdx.x;
    const int tx = tid & 15;
    const int ty = tid >> 4;
    const int lrow = tid >> 2;   // 0..63
    const int lc4  = tid & 3;    // 0..3

    float acc[8][8];
    #pragma unroll
    for (int r = 0; r < 8; r++)
        #pragma unroll
        for (int c = 0; c < 8; c++) acc[r][c] = 0.f;

    for (int k0 = 0; k0 < K; k0 += 16) {
        #pragma unroll
        for (int hh = 0; hh < 2; hh++) {
            const int row = lrow + hh * 64;
            float4 va = *(const float4*)(Ab + (size_t)(bm0 + row) * K + k0 + lc4 * 4);
            As[lc4 * 4 + 0][row] = va.x;
            As[lc4 * 4 + 1][row] = va.y;
            As[lc4 * 4 + 2][row] = va.z;
            As[lc4 * 4 + 3][row] = va.w;
            float4 vb = *(const float4*)(Wb + (size_t)(bn0 + row) * K + k0 + lc4 * 4);
            Bs[lc4 * 4 + 0][row] = vb.x;
            Bs[lc4 * 4 + 1][row] = vb.y;
            Bs[lc4 * 4 + 2][row] = vb.z;
            Bs[lc4 * 4 + 3][row] = vb.w;
        }
        __syncthreads();
        #pragma unroll
        for (int kk = 0; kk < 16; kk++) {
            float ar[8], br[8];
            #pragma unroll
            for (int r = 0; r < 8; r++) ar[r] = As[kk][ty * 8 + r];
            #pragma unroll
            for (int c = 0; c < 8; c++) br[c] = Bs[kk][tx * 8 + c];
            #pragma unroll
            for (int r = 0; r < 8; r++)
                #pragma unroll
                for (int c = 0; c < 8; c++)
                    acc[r][c] += ar[r] * br[c];
        }
        __syncthreads();
    }

    #pragma unroll
    for (int r = 0; r < 8; r++) {
        const int m = bm0 + ty * 8 + r;
        #pragma unroll
        for (int c = 0; c < 8; c++) {
            const int o = bn0 + tx * 8 + c;
            float vv = acc[r][c];
            if (blade == 0) vv += bias[o];
            if (Rb) vv += Rb[(size_t)m * N + o];
            Yb[(size_t)m * N + o] = vv;
        }
    }
}

// -------- attention over SEQ=25, per (batch, head) block --------
__global__ void k_attn(const float* __restrict__ q, const float* __restrict__ k,
                       const float* __restrict__ v, float* __restrict__ o) {
    const int b = blockIdx.x / HHH;
    const int h = blockIdx.x % HHH;
    __shared__ float sq[8][SEQL][DHD];
    __shared__ float sk[8][SEQL][DHD];
    __shared__ float sv[8][SEQL][DHD];
    __shared__ float ss[SEQL][SEQL + 1];
    const int tid = threadIdx.x;
    const size_t rowbase = (size_t)b * SEQL * DCH + h * DHD;

    for (int e = tid; e < 8 * SEQL * DHD; e += 128) {
        int i = e / (SEQL * DHD);
        int r = e % (SEQL * DHD);
        int s = r / DHD, d = r % DHD;
        size_t gix = (size_t)i * PS + rowbase + (size_t)s * DCH + d;
        sq[i][s][d] = q[gix];
        sk[i][s][d] = k[gix];
        sv[i][s][d] = v[gix];
    }
    __syncthreads();

    const float scale = 0.08838834764831845f; // 1/sqrt(128)
    for (int e = tid; e < SEQL * SEQL; e += 128) {
        int s = e / SEQL, t = e % SEQL;
        float acc = 0.f;
        #pragma unroll
        for (int i = 0; i < 8; i++)
            #pragma unroll
            for (int d = 0; d < DHD; d++)
                acc += sq[i][s][d] * sk[i][t][d];
        ss[s][t] = acc * scale;
    }
    __syncthreads();

    if (tid < SEQL) {
        int s = tid;
        float m = -1e30f;
        for (int t = 0; t < SEQL; t++) m = fmaxf(m, ss[s][t]);
        float sum = 0.f;
        for (int t = 0; t < SEQL; t++) { float e = expf(ss[s][t] - m); ss[s][t] = e; sum += e; }
        float r = 1.f / sum;
        for (int t = 0; t < SEQL; t++) ss[s][t] *= r;
    }
    __syncthreads();

    for (int e = tid; e < 8 * SEQL * DHD; e += 128) {
        int i = e / (SEQL * DHD);
        int r = e % (SEQL * DHD);
        int s = r / DHD, d = r % DHD;
        float acc = 0.f;
        #pragma unroll
        for (int t = 0; t < SEQL; t++) acc += ss[s][t] * sv[i][t][d];
        o[(size_t)i * PS + rowbase + (size_t)s * DCH + d] = acc;
    }
}

// -------- geometric product (Cl(3,0)) on [8][N][256] --------
__global__ void k_gp(const float* __restrict__ xl, const float* __restrict__ xr,
                     float* __restrict__ out) {
    size_t idx = (size_t)blockIdx.x * 256 + threadIdx.x;
    float a[8], b[8];
    #pragma unroll
    for (int i = 0; i < 8; i++) { a[i] = xl[(size_t)i * PS2 + idx]; b[i] = xr[(size_t)i * PS2 + idx]; }
    float r[8];
    r[0] = a[0]*b[0] + a[1]*b[1] + a[2]*b[2] + a[3]*b[3] - a[4]*b[4] - a[5]*b[5] - a[6]*b[6] - a[7]*b[7];
    r[1] = a[0]*b[1] + a[1]*b[0] - a[2]*b[4] + a[4]*b[2] - a[3]*b[5] + a[5]*b[3] - a[6]*b[7] - a[7]*b[6];
    r[2] = a[0]*b[2] + a[2]*b[0] + a[1]*b[4] - a[4]*b[1] - a[3]*b[6] + a[6]*b[3] + a[5]*b[7] + a[7]*b[5];
    r[3] = a[0]*b[3] + a[3]*b[0] + a[1]*b[5] - a[5]*b[1] + a[2]*b[6] - a[6]*b[2] - a[4]*b[7] - a[7]*b[4];
    r[4] = a[0]*b[4] + a[4]*b[0] + a[1]*b[2] - a[2]*b[1] + a[3]*b[7] + a[7]*b[3] - a[5]*b[6] + a[6]*b[5];
    r[5] = a[0]*b[5] + a[5]*b[0] + a[1]*b[3] - a[3]*b[1] - a[2]*b[7] - a[7]*b[2] + a[4]*b[6] - a[6]*b[4];
    r[6] = a[0]*b[6] + a[6]*b[0] + a[2]*b[3] - a[3]*b[2] + a[1]*b[7] + a[7]*b[1] - a[4]*b[5] + a[5]*b[4];
    r[7] = a[0]*b[7] + a[7]*b[0] + a[1]*b[6] + a[6]*b[1] - a[2]*b[5] - a[5]*b[2] + a[3]*b[4] + a[4]*b[3];
    #pragma unroll
    for (int i = 0; i < 8; i++) out[(size_t)i * PS2 + idx] = r[i];
}

// -------- MVSiLU on [8][N][256], in-place --------
__global__ void k_silu(const float* __restrict__ sa, const float* __restrict__ sb,
                       float* __restrict__ x) {
    size_t idx = (size_t)blockIdx.x * 256 + threadIdx.x;
    int c = (int)(idx & 255);
    float v[8];
    #pragma unroll
    for (int i = 0; i < 8; i++) v[i] = x[(size_t)i * PS2 + idx];
    float inv0 = v[0];
    float inv1 = v[1]*v[1] + v[2]*v[2] + v[3]*v[3];
    float inv2 = v[4]*v[4] + v[5]*v[5] + v[6]*v[6];
    float inv3 = v[7]*v[7];
    float s0 = 1.f / (1.f + expf(-(sa[c*4+0]*inv0 + sb[c*4+0])));
    float s1 = 1.f / (1.f + expf(-(sa[c*4+1]*inv1 + sb[c*4+1])));
    float s2 = 1.f / (1.f + expf(-(sa[c*4+2]*inv2 + sb[c*4+2])));
    float s3 = 1.f / (1.f + expf(-(sa[c*4+3]*inv3 + sb[c*4+3])));
    x[(size_t)0*PS2 + idx] = v[0]*s0;
    x[(size_t)1*PS2 + idx] = v[1]*s1;
    x[(size_t)2*PS2 + idx] = v[2]*s1;
    x[(size_t)3*PS2 + idx] = v[3]*s1;
    x[(size_t)4*PS2 + idx] = v[4]*s2;
    x[(size_t)5*PS2 + idx] = v[5]*s2;
    x[(size_t)6*PS2 + idx] = v[6]*s2;
    x[(size_t)7*PS2 + idx] = v[7]*s3;
}

// -------- final: out[n][c][i] = x4[i][n][c] + ff[i][n][c] (blade-major -> interleaved) --------
__global__ void k_final(const float* __restrict__ x4, const float* __restrict__ ff,
                        float* __restrict__ out) {
    size_t idx = (size_t)blockIdx.x * 256 + threadIdx.x;  // over N*D
    float v[8];
    #pragma unroll
    for (int i = 0; i < 8; i++) v[i] = x4[(size_t)i * PS + idx] + ff[(size_t)i * PS + idx];
    float4* o = (float4*)(out + idx * 8);
    o[0] = make_float4(v[0], v[1], v[2], v[3]);
    o[1] = make_float4(v[4], v[5], v[6], v[7]);
}

extern "C" void kernel_launch(void* const* d_in, const int* in_sizes, int n_in,
                              void* d_out, int out_size) {
    const float* src  = (const float*)d_in[0];
    const float* ln1a = (const float*)d_in[1];
    const float* ln2a = (const float*)d_in[2];
    const float* ln3a = (const float*)d_in[3];
    const float* wq  = (const float*)d_in[4];  const float* bq  = (const float*)d_in[5];
    const float* wk  = (const float*)d_in[6];  const float* bk  = (const float*)d_in[7];
    const float* wv  = (const float*)d_in[8];  const float* bv  = (const float*)d_in[9];
    const float* wo  = (const float*)d_in[10]; const float* bo  = (const float*)d_in[11];
    const float* gw1 = (const float*)d_in[12]; const float* gb1 = (const float*)d_in[13];
    const float* gw2 = (const float*)d_in[14]; const float* gb2 = (const float*)d_in[15];
    const float* gw3 = (const float*)d_in[16]; const float* gb3 = (const float*)d_in[17];
    const float* gna = (const float*)d_in[18];
    const float* mw1 = (const float*)d_in[19]; const float* mb1 = (const float*)d_in[20];
    const float* sa  = (const float*)d_in[21]; const float* sb  = (const float*)d_in[22];
    const float* mw2 = (const float*)d_in[23]; const float* mb2 = (const float*)d_in[24];
    float* out = (float*)d_out;

    float *S, *W4;
    cudaGetSymbolAddress((void**)&S, g_scratch);
    cudaGetSymbolAddress((void**)&W4, g_w4);

    float* B0 = S;                         // srcT
    float* B1 = S + (size_t)1 * UNIT;      // h1 -> x1
    float* B2 = S + (size_t)2 * UNIT;      // q  -> x2
    float* B3 = S + (size_t)3 * UNIT;      // k  -> g1 -> ff
    float* B4 = S + (size_t)4 * UNIT;      // v  -> x3
    float* B5 = S + (size_t)5 * UNIT;      // attn_o -> x4
    float* B6 = S + (size_t)6 * UNIT;      // xl -> m1/m2   (2 units)
    float* B7 = S + (size_t)8 * UNIT;      // xr            (2 units)
    float* B8 = S + (size_t)10 * UNIT;     // g0            (2 units)

    // expanded weight offsets
    float* Wq = W4 + 0;       float* Wk = W4 + 65536;  float* Wv = W4 + 131072;
    float* Wo = W4 + 196608;
    float* Wg1 = W4 + 262144; float* Wg2 = W4 + 393216; float* Wg3 = W4 + 524288;
    float* Wm1 = W4 + 655360; float* Wm2 = W4 + 786432;

    k_expand<<<256, 256>>>(wq, Wq, 65536);
    k_expand<<<256, 256>>>(wk, Wk, 65536);
    k_expand<<<256, 256>>>(wv, Wv, 65536);
    k_expand<<<256, 256>>>(wo, Wo, 65536);
    k_expand<<<512, 256>>>(gw1, Wg1, 131072);
    k_expand<<<512, 256>>>(gw2, Wg2, 131072);
    k_expand<<<512, 256>>>(gw3, Wg3, 131072);
    k_expand<<<512, 256>>>(mw1, Wm1, 131072);
    k_expand<<<512, 256>>>(mw2, Wm2, 131072);

    // 1) transpose + ln1
    k_tr_ln1<<<NND, 128>>>(src, ln1a, B0, B1);

    // 2) q, k, v
    dim3 g128(1, 200, 8), g256(2, 200, 8);
    k_sgemm<<<g128, 256>>>(B1, Wq, bq, nullptr, B2, NND, 128, 128);
    k_sgemm<<<g128, 256>>>(B1, Wk, bk, nullptr, B3, NND, 128, 128);
    k_sgemm<<<g128, 256>>>(B1, Wv, bv, nullptr, B4, NND, 128, 128);

    // 3) attention -> o in B5
    k_attn<<<1024 * HHH, 128>>>(B2, B3, B4, B5);

    // 4) x1 = srcT + wo(o)   (residual fused in epilogue)
    k_sgemm<<<g128, 256>>>(B5, Wo, bo, B0, B1, NND, 128, 128);

    // 5) x2 = ln2(x1)
    k_ln<<<NND, 128>>>(B1, ln2a, nullptr, B2);

    // 6) GP branch
    k_sgemm<<<g256, 256>>>(B2, Wg1, gb1, nullptr, B6, NND, 256, 128);
    k_sgemm<<<g256, 256>>>(B2, Wg2, gb2, nullptr, B7, NND, 256, 128);
    k_gp<<<25600, 256>>>(B6, B7, B8);
    k_sgemm<<<g128, 256>>>(B8, Wg3, gb3, nullptr, B3, NND, 128, 256);
    // x3 = x2 + ln(g1, gna)
    k_ln<<<NND, 128>>>(B3, gna, B2, B4);

    // 7) x4 = ln3(x3)
    k_ln<<<NND, 128>>>(B4, ln3a, nullptr, B5);

    // 8) MLP
    k_sgemm<<<g256, 256>>>(B5, Wm1, mb1, nullptr, B6, NND, 256, 128);
    k_silu<<<25600, 256>>>(sa, sb, B6);
    k_sgemm<<<g128, 256>>>(B6, Wm2, mb2, nullptr, B3, NND, 128, 256);

    // 9) out = x4 + ff, transposed back to [N, D, 8]
    k_final<<<12800, 256>>>(B5, B3, out);

    (void)in_sizes; (void)n_in; (void)out_size;
}

// round 2
// speedup vs baseline: 2.0234x; 2.0234x over previous
#include <cuda_runtime.h>
#include <math.h>

// Problem constants
#define NND   25600                  // num nodes (B*SEQ)
#define DCH   128                    // channels
#define SEQL  25
#define HHH   8
#define DHD   16
#define PS    (25600*128)            // plane stride for D=128 blade-major arrays
#define PS2   (25600*256)            // plane stride for 2D=256 arrays
#define UNIT  (8*25600*128)          // one [8][N][128] tensor, floats

// Scratch: 12 units (allowed: __device__ globals, no allocs)
__device__ float g_scratch[12u * (unsigned)UNIT];
// Expanded per-grade weights: [grade(4)][out][in] for each of 9 linears
__device__ float g_w4[917504];

__device__ __forceinline__ unsigned f2tf32(float f) {
    unsigned r;
    asm("cvt.rna.tf32.f32 %0, %1;" : "=r"(r) : "f"(f));
    return r;
}

// ---------------- weight expansion: w[o][m][g] -> out[g][o*m] ----------------
__global__ void k_expand(const float* __restrict__ w, float* __restrict__ out, int total) {
    int i = blockIdx.x * blockDim.x + threadIdx.x;
    if (i < total) {
        int om = total >> 2;           // O*M
        int g = i / om, r = i % om;
        out[i] = w[r * 4 + g];
    }
}

// -------- transpose [N,D,8] -> blade-major [8][N][D], fused with mv_layernorm(ln1) --------
__global__ void k_tr_ln1(const float* __restrict__ src, const float* __restrict__ a,
                         float* __restrict__ srcT, float* __restrict__ h1) {
    int n = blockIdx.x, c = threadIdx.x;
    const float* p = src + ((size_t)n * DCH + c) * 8;
    float4 x0 = *(const float4*)p;
    float4 x1 = *(const float4*)(p + 4);
    float v[8] = {x0.x, x0.y, x0.z, x0.w, x1.x, x1.y, x1.z, x1.w};
    float s = 0.f;
    #pragma unroll
    for (int i = 0; i < 8; i++) s += v[i] * v[i];
    float nr = sqrtf(s);
    __shared__ float red[128];
    red[c] = nr; __syncthreads();
    for (int st = 64; st > 0; st >>= 1) {
        if (c < st) red[c] += red[c + st];
        __syncthreads();
    }
    float inv = 1.f / (red[0] * (1.f / 128.f) + 1e-6f);
    float ac = a[c];
    size_t base = (size_t)n * DCH + c;
    #pragma unroll
    for (int i = 0; i < 8; i++) {
        srcT[(size_t)i * PS + base] = v[i];
        h1[(size_t)i * PS + base]   = ac * v[i] * inv;
    }
}

// -------- mv_layernorm on blade-major [8][N][128], optional residual add --------
__global__ void k_ln(const float* __restrict__ x, const float* __restrict__ a,
                     const float* __restrict__ res, float* __restrict__ out) {
    int n = blockIdx.x, c = threadIdx.x;
    size_t base = (size_t)n * DCH + c;
    float v[8];
    #pragma unroll
    for (int i = 0; i < 8; i++) v[i] = x[(size_t)i * PS + base];
    float s = 0.f;
    #pragma unroll
    for (int i = 0; i < 8; i++) s += v[i] * v[i];
    float nr = sqrtf(s);
    __shared__ float red[128];
    red[c] = nr; __syncthreads();
    for (int st = 64; st > 0; st >>= 1) {
        if (c < st) red[c] += red[c + st];
        __syncthreads();
    }
    float inv = 1.f / (red[0] * (1.f / 128.f) + 1e-6f);
    float ac = a[c];
    #pragma unroll
    for (int i = 0; i < 8; i++) {
        float r = res ? res[(size_t)i * PS + base] : 0.f;
        out[(size_t)i * PS + base] = r + ac * v[i] * inv;
    }
}

// ============ TF32 tensor-core blade-GEMM ============
// Y[i][n][o] = sum_m A[i][n][m] * W[grade(i)][o][m] (+bias@blade0, +res)
// BM=128, BN=128, BK=16; 8 warps (2x4), warp tile 64x32 via m16n8k8 mma.
__global__ __launch_bounds__(256, 2)
void k_mma(const float* __restrict__ A, const float* __restrict__ W,
           const float* __restrict__ bias, const float* __restrict__ Res,
           float* __restrict__ Y, int M, int N, int K) {
    const int blade = blockIdx.z;
    const int g = (blade == 0) ? 0 : (blade <= 3) ? 1 : (blade <= 6) ? 2 : 3;
    const float* Ab = A + (size_t)blade * M * K;
    const float* Wb = W + (size_t)g * N * K;
    float* Yb = Y + (size_t)blade * M * N;
    const float* Rb = Res ? (Res + (size_t)blade * M * N) : nullptr;

    const int bm0 = blockIdx.y * 128;
    const int bn0 = blockIdx.x * 128;

    __shared__ unsigned As[128][20];   // [m][k], stride 20 -> conflict-free frag loads
    __shared__ unsigned Bs[128][20];   // [n][k]

    const int tid = threadIdx.x;
    const int warp = tid >> 5;
    const int lane = tid & 31;
    const int wm = (warp >> 2) * 64;   // warp M offset (0/64)
    const int wn = (warp & 3) * 32;    // warp N offset (0/32/64/96)
    const int gq = lane >> 2;          // group id 0..7
    const int tq = lane & 3;           // thread-in-group 0..3

    const int lrow = tid >> 2;         // 0..63 (loader row)
    const int lc4  = tid & 3;          // 0..3  (loader k-quad)

    float acc[4][4][4];
    #pragma unroll
    for (int mt = 0; mt < 4; mt++)
        #pragma unroll
        for (int nt = 0; nt < 4; nt++)
            #pragma unroll
            for (int e = 0; e < 4; e++) acc[mt][nt][e] = 0.f;

    // prologue: load k0=0 tile
    float4 sa0 = *(const float4*)(Ab + (size_t)(bm0 + lrow) * K + lc4 * 4);
    float4 sa1 = *(const float4*)(Ab + (size_t)(bm0 + lrow + 64) * K + lc4 * 4);
    float4 sb0 = *(const float4*)(Wb + (size_t)(bn0 + lrow) * K + lc4 * 4);
    float4 sb1 = *(const float4*)(Wb + (size_t)(bn0 + lrow + 64) * K + lc4 * 4);
    As[lrow][lc4*4+0] = f2tf32(sa0.x); As[lrow][lc4*4+1] = f2tf32(sa0.y);
    As[lrow][lc4*4+2] = f2tf32(sa0.z); As[lrow][lc4*4+3] = f2tf32(sa0.w);
    As[lrow+64][lc4*4+0] = f2tf32(sa1.x); As[lrow+64][lc4*4+1] = f2tf32(sa1.y);
    As[lrow+64][lc4*4+2] = f2tf32(sa1.z); As[lrow+64][lc4*4+3] = f2tf32(sa1.w);
    Bs[lrow][lc4*4+0] = f2tf32(sb0.x); Bs[lrow][lc4*4+1] = f2tf32(sb0.y);
    Bs[lrow][lc4*4+2] = f2tf32(sb0.z); Bs[lrow][lc4*4+3] = f2tf32(sb0.w);
    Bs[lrow+64][lc4*4+0] = f2tf32(sb1.x); Bs[lrow+64][lc4*4+1] = f2tf32(sb1.y);
    Bs[lrow+64][lc4*4+2] = f2tf32(sb1.z); Bs[lrow+64][lc4*4+3] = f2tf32(sb1.w);

    for (int k0 = 0; k0 < K; k0 += 16) {
        __syncthreads();
        const bool has_next = (k0 + 16) < K;
        if (has_next) {
            const int kn = k0 + 16;
            sa0 = *(const float4*)(Ab + (size_t)(bm0 + lrow) * K + kn + lc4 * 4);
            sa1 = *(const float4*)(Ab + (size_t)(bm0 + lrow + 64) * K + kn + lc4 * 4);
            sb0 = *(const float4*)(Wb + (size_t)(bn0 + lrow) * K + kn + lc4 * 4);
            sb1 = *(const float4*)(Wb + (size_t)(bn0 + lrow + 64) * K + kn + lc4 * 4);
        }

        #pragma unroll
        for (int ks = 0; ks < 2; ks++) {
            const int kb = ks * 8;
            unsigned af[4][4];
            #pragma unroll
            for (int mt = 0; mt < 4; mt++) {
                const int row = wm + mt * 16 + gq;
                af[mt][0] = As[row][kb + tq];
                af[mt][1] = As[row + 8][kb + tq];
                af[mt][2] = As[row][kb + tq + 4];
                af[mt][3] = As[row + 8][kb + tq + 4];
            }
            unsigned bf[4][2];
            #pragma unroll
            for (int nt = 0; nt < 4; nt++) {
                const int col = wn + nt * 8 + gq;
                bf[nt][0] = Bs[col][kb + tq];
                bf[nt][1] = Bs[col][kb + tq + 4];
            }
            #pragma unroll
            for (int mt = 0; mt < 4; mt++)
                #pragma unroll
                for (int nt = 0; nt < 4; nt++) {
                    asm volatile(
                        "mma.sync.aligned.m16n8k8.row.col.f32.tf32.tf32.f32 "
                        "{%0,%1,%2,%3}, {%4,%5,%6,%7}, {%8,%9}, {%0,%1,%2,%3};"
                        : "+f"(acc[mt][nt][0]), "+f"(acc[mt][nt][1]),
                          "+f"(acc[mt][nt][2]), "+f"(acc[mt][nt][3])
                        : "r"(af[mt][0]), "r"(af[mt][1]), "r"(af[mt][2]), "r"(af[mt][3]),
                          "r"(bf[nt][0]), "r"(bf[nt][1]));
                }
        }

        if (has_next) {
            __syncthreads();
            As[lrow][lc4*4+0] = f2tf32(sa0.x); As[lrow][lc4*4+1] = f2tf32(sa0.y);
            As[lrow][lc4*4+2] = f2tf32(sa0.z); As[lrow][lc4*4+3] = f2tf32(sa0.w);
            As[lrow+64][lc4*4+0] = f2tf32(sa1.x); As[lrow+64][lc4*4+1] = f2tf32(sa1.y);
            As[lrow+64][lc4*4+2] = f2tf32(sa1.z); As[lrow+64][lc4*4+3] = f2tf32(sa1.w);
            Bs[lrow][lc4*4+0] = f2tf32(sb0.x); Bs[lrow][lc4*4+1] = f2tf32(sb0.y);
            Bs[lrow][lc4*4+2] = f2tf32(sb0.z); Bs[lrow][lc4*4+3] = f2tf32(sb0.w);
            Bs[lrow+64][lc4*4+0] = f2tf32(sb1.x); Bs[lrow+64][lc4*4+1] = f2tf32(sb1.y);
            Bs[lrow+64][lc4*4+2] = f2tf32(sb1.z); Bs[lrow+64][lc4*4+3] = f2tf32(sb1.w);
        }
    }

    // epilogue: c0:(g,2t) c1:(g,2t+1) c2:(g+8,2t) c3:(g+8,2t+1)
    #pragma unroll
    for (int mt = 0; mt < 4; mt++) {
        #pragma unroll
        for (int nt = 0; nt < 4; nt++) {
            const int r0 = bm0 + wm + mt * 16 + gq;
            const int c0 = bn0 + wn + nt * 8 + tq * 2;
            float v0 = acc[mt][nt][0], v1 = acc[mt][nt][1];
            float v2 = acc[mt][nt][2], v3 = acc[mt][nt][3];
            if (blade == 0) {
                float b0 = bias[c0], b1 = bias[c0 + 1];
                v0 += b0; v1 += b1; v2 += b0; v3 += b1;
            }
            if (Rb) {
                const float2 rr0 = *(const float2*)(Rb + (size_t)r0 * N + c0);
                const float2 rr1 = *(const float2*)(Rb + (size_t)(r0 + 8) * N + c0);
                v0 += rr0.x; v1 += rr0.y; v2 += rr1.x; v3 += rr1.y;
            }
            *(float2*)(Yb + (size_t)r0 * N + c0) = make_float2(v0, v1);
            *(float2*)(Yb + (size_t)(r0 + 8) * N + c0) = make_float2(v2, v3);
        }
    }
}

// -------- attention over SEQ=25, per (batch, head) block --------
__global__ void k_attn(const float* __restrict__ q, const float* __restrict__ k,
                       const float* __restrict__ v, float* __restrict__ o) {
    const int b = blockIdx.x / HHH;
    const int h = blockIdx.x % HHH;
    __shared__ float sq[8][SEQL][DHD];
    __shared__ float sk[8][SEQL][DHD];
    __shared__ float sv[8][SEQL][DHD];
    __shared__ float ss[SEQL][SEQL + 1];
    const int tid = threadIdx.x;
    const size_t rowbase = (size_t)b * SEQL * DCH + h * DHD;

    for (int e = tid; e < 8 * SEQL * DHD; e += 128) {
        int i = e / (SEQL * DHD);
        int r = e % (SEQL * DHD);
        int s = r / DHD, d = r % DHD;
        size_t gix = (size_t)i * PS + rowbase + (size_t)s * DCH + d;
        sq[i][s][d] = q[gix];
        sk[i][s][d] = k[gix];
        sv[i][s][d] = v[gix];
    }
    __syncthreads();

    const float scale = 0.08838834764831845f; // 1/sqrt(128)
    for (int e = tid; e < SEQL * SEQL; e += 128) {
        int s = e / SEQL, t = e % SEQL;
        float acc = 0.f;
        #pragma unroll
        for (int i = 0; i < 8; i++)
            #pragma unroll
            for (int d = 0; d < DHD; d++)
                acc += sq[i][s][d] * sk[i][t][d];
        ss[s][t] = acc * scale;
    }
    __syncthreads();

    if (tid < SEQL) {
        int s = tid;
        float m = -1e30f;
        for (int t = 0; t < SEQL; t++) m = fmaxf(m, ss[s][t]);
        float sum = 0.f;
        for (int t = 0; t < SEQL; t++) { float e = expf(ss[s][t] - m); ss[s][t] = e; sum += e; }
        float r = 1.f / sum;
        for (int t = 0; t < SEQL; t++) ss[s][t] *= r;
    }
    __syncthreads();

    for (int e = tid; e < 8 * SEQL * DHD; e += 128) {
        int i = e / (SEQL * DHD);
        int r = e % (SEQL * DHD);
        int s = r / DHD, d = r % DHD;
        float acc = 0.f;
        #pragma unroll
        for (int t = 0; t < SEQL; t++) acc += ss[s][t] * sv[i][t][d];
        o[(size_t)i * PS + rowbase + (size_t)s * DCH + d] = acc;
    }
}

// -------- geometric product (Cl(3,0)) on [8][N][256] --------
__global__ void k_gp(const float* __restrict__ xl, const float* __restrict__ xr,
                     float* __restrict__ out) {
    size_t idx = (size_t)blockIdx.x * 256 + threadIdx.x;
    float a[8], b[8];
    #pragma unroll
    for (int i = 0; i < 8; i++) { a[i] = xl[(size_t)i * PS2 + idx]; b[i] = xr[(size_t)i * PS2 + idx]; }
    float r[8];
    r[0] = a[0]*b[0] + a[1]*b[1] + a[2]*b[2] + a[3]*b[3] - a[4]*b[4] - a[5]*b[5] - a[6]*b[6] - a[7]*b[7];
    r[1] = a[0]*b[1] + a[1]*b[0] - a[2]*b[4] + a[4]*b[2] - a[3]*b[5] + a[5]*b[3] - a[6]*b[7] - a[7]*b[6];
    r[2] = a[0]*b[2] + a[2]*b[0] + a[1]*b[4] - a[4]*b[1] - a[3]*b[6] + a[6]*b[3] + a[5]*b[7] + a[7]*b[5];
    r[3] = a[0]*b[3] + a[3]*b[0] + a[1]*b[5] - a[5]*b[1] + a[2]*b[6] - a[6]*b[2] - a[4]*b[7] - a[7]*b[4];
    r[4] = a[0]*b[4] + a[4]*b[0] + a[1]*b[2] - a[2]*b[1] + a[3]*b[7] + a[7]*b[3] - a[5]*b[6] + a[6]*b[5];
    r[5] = a[0]*b[5] + a[5]*b[0] + a[1]*b[3] - a[3]*b[1] - a[2]*b[7] - a[7]*b[2] + a[4]*b[6] - a[6]*b[4];
    r[6] = a[0]*b[6] + a[6]*b[0] + a[2]*b[3] - a[3]*b[2] + a[1]*b[7] + a[7]*b[1] - a[4]*b[5] + a[5]*b[4];
    r[7] = a[0]*b[7] + a[7]*b[0] + a[1]*b[6] + a[6]*b[1] - a[2]*b[5] - a[5]*b[2] + a[3]*b[4] + a[4]*b[3];
    #pragma unroll
    for (int i = 0; i < 8; i++) out[(size_t)i * PS2 + idx] = r[i];
}

// -------- MVSiLU on [8][N][256], in-place --------
__global__ void k_silu(const float* __restrict__ sa, const float* __restrict__ sb,
                       float* __restrict__ x) {
    size_t idx = (size_t)blockIdx.x * 256 + threadIdx.x;
    int c = (int)(idx & 255);
    float v[8];
    #pragma unroll
    for (int i = 0; i < 8; i++) v[i] = x[(size_t)i * PS2 + idx];
    float inv0 = v[0];
    float inv1 = v[1]*v[1] + v[2]*v[2] + v[3]*v[3];
    float inv2 = v[4]*v[4] + v[5]*v[5] + v[6]*v[6];
    float inv3 = v[7]*v[7];
    float s0 = 1.f / (1.f + expf(-(sa[c*4+0]*inv0 + sb[c*4+0])));
    float s1 = 1.f / (1.f + expf(-(sa[c*4+1]*inv1 + sb[c*4+1])));
    float s2 = 1.f / (1.f + expf(-(sa[c*4+2]*inv2 + sb[c*4+2])));
    float s3 = 1.f / (1.f + expf(-(sa[c*4+3]*inv3 + sb[c*4+3])));
    x[(size_t)0*PS2 + idx] = v[0]*s0;
    x[(size_t)1*PS2 + idx] = v[1]*s1;
    x[(size_t)2*PS2 + idx] = v[2]*s1;
    x[(size_t)3*PS2 + idx] = v[3]*s1;
    x[(size_t)4*PS2 + idx] = v[4]*s2;
    x[(size_t)5*PS2 + idx] = v[5]*s2;
    x[(size_t)6*PS2 + idx] = v[6]*s2;
    x[(size_t)7*PS2 + idx] = v[7]*s3;
}

// -------- final: out[n][c][i] = x4[i][n][c] + ff[i][n][c] (blade-major -> interleaved) --------
__global__ void k_final(const float* __restrict__ x4, const float* __restrict__ ff,
                        float* __restrict__ out) {
    size_t idx = (size_t)blockIdx.x * 256 + threadIdx.x;  // over N*D
    float v[8];
    #pragma unroll
    for (int i = 0; i < 8; i++) v[i] = x4[(size_t)i * PS + idx] + ff[(size_t)i * PS + idx];
    float4* o = (float4*)(out + idx * 8);
    o[0] = make_float4(v[0], v[1], v[2], v[3]);
    o[1] = make_float4(v[4], v[5], v[6], v[7]);
}

extern "C" void kernel_launch(void* const* d_in, const int* in_sizes, int n_in,
                              void* d_out, int out_size) {
    const float* src  = (const float*)d_in[0];
    const float* ln1a = (const float*)d_in[1];
    const float* ln2a = (const float*)d_in[2];
    const float* ln3a = (const float*)d_in[3];
    const float* wq  = (const float*)d_in[4];  const float* bq  = (const float*)d_in[5];
    const float* wk  = (const float*)d_in[6];  const float* bk  = (const float*)d_in[7];
    const float* wv  = (const float*)d_in[8];  const float* bv  = (const float*)d_in[9];
    const float* wo  = (const float*)d_in[10]; const float* bo  = (const float*)d_in[11];
    const float* gw1 = (const float*)d_in[12]; const float* gb1 = (const float*)d_in[13];
    const float* gw2 = (const float*)d_in[14]; const float* gb2 = (const float*)d_in[15];
    const float* gw3 = (const float*)d_in[16]; const float* gb3 = (const float*)d_in[17];
    const float* gna = (const float*)d_in[18];
    const float* mw1 = (const float*)d_in[19]; const float* mb1 = (const float*)d_in[20];
    const float* sa  = (const float*)d_in[21]; const float* sb  = (const float*)d_in[22];
    const float* mw2 = (const float*)d_in[23]; const float* mb2 = (const float*)d_in[24];
    float* out = (float*)d_out;

    float *S, *W4;
    cudaGetSymbolAddress((void**)&S, g_scratch);
    cudaGetSymbolAddress((void**)&W4, g_w4);

    float* B0 = S;                         // srcT
    float* B1 = S + (size_t)1 * UNIT;      // h1 -> x1
    float* B2 = S + (size_t)2 * UNIT;      // q  -> x2
    float* B3 = S + (size_t)3 * UNIT;      // k  -> g1 -> ff
    float* B4 = S + (size_t)4 * UNIT;      // v  -> x3
    float* B5 = S + (size_t)5 * UNIT;      // attn_o -> x4
    float* B6 = S + (size_t)6 * UNIT;      // xl -> m1/m2   (2 units)
    float* B7 = S + (size_t)8 * UNIT;      // xr            (2 units)
    float* B8 = S + (size_t)10 * UNIT;     // g0            (2 units)

    // expanded weight offsets
    float* Wq = W4 + 0;       float* Wk = W4 + 65536;  float* Wv = W4 + 131072;
    float* Wo = W4 + 196608;
    float* Wg1 = W4 + 262144; float* Wg2 = W4 + 393216; float* Wg3 = W4 + 524288;
    float* Wm1 = W4 + 655360; float* Wm2 = W4 + 786432;

    k_expand<<<256, 256>>>(wq, Wq, 65536);
    k_expand<<<256, 256>>>(wk, Wk, 65536);
    k_expand<<<256, 256>>>(wv, Wv, 65536);
    k_expand<<<256, 256>>>(wo, Wo, 65536);
    k_expand<<<512, 256>>>(gw1, Wg1, 131072);
    k_expand<<<512, 256>>>(gw2, Wg2, 131072);
    k_expand<<<512, 256>>>(gw3, Wg3, 131072);
    k_expand<<<512, 256>>>(mw1, Wm1, 131072);
    k_expand<<<512, 256>>>(mw2, Wm2, 131072);

    // 1) transpose + ln1
    k_tr_ln1<<<NND, 128>>>(src, ln1a, B0, B1);

    // 2) q, k, v
    dim3 g128(1, 200, 8), g256(2, 200, 8);
    k_mma<<<g128, 256>>>(B1, Wq, bq, nullptr, B2, NND, 128, 128);
    k_mma<<<g128, 256>>>(B1, Wk, bk, nullptr, B3, NND, 128, 128);
    k_mma<<<g128, 256>>>(B1, Wv, bv, nullptr, B4, NND, 128, 128);

    // 3) attention -> o in B5
    k_attn<<<1024 * HHH, 128>>>(B2, B3, B4, B5);

    // 4) x1 = srcT + wo(o)   (residual fused in epilogue)
    k_mma<<<g128, 256>>>(B5, Wo, bo, B0, B1, NND, 128, 128);

    // 5) x2 = ln2(x1)
    k_ln<<<NND, 128>>>(B1, ln2a, nullptr, B2);

    // 6) GP branch
    k_mma<<<g256, 256>>>(B2, Wg1, gb1, nullptr, B6, NND, 256, 128);
    k_mma<<<g256, 256>>>(B2, Wg2, gb2, nullptr, B7, NND, 256, 128);
    k_gp<<<25600, 256>>>(B6, B7, B8);
    k_mma<<<g128, 256>>>(B8, Wg3, gb3, nullptr, B3, NND, 128, 256);
    // x3 = x2 + ln(g1, gna)
    k_ln<<<NND, 128>>>(B3, gna, B2, B4);

    // 7) x4 = ln3(x3)
    k_ln<<<NND, 128>>>(B4, ln3a, nullptr, B5);

    // 8) MLP
    k_mma<<<g256, 256>>>(B5, Wm1, mb1, nullptr, B6, NND, 256, 128);
    k_silu<<<25600, 256>>>(sa, sb, B6);
    k_mma<<<g128, 256>>>(B6, Wm2, mb2, nullptr, B3, NND, 128, 256);

    // 9) out = x4 + ff, transposed back to [N, D, 8]
    k_final<<<12800, 256>>>(B5, B3, out);

    (void)in_sizes; (void)n_in; (void)out_size;
}